// round 12
// baseline (speedup 1.0000x reference)
#include <cuda_runtime.h>
#include <cstdint>

// Problem constants (B=8, H=16, S=1024, D=64)
#define TB   256      // threads per block
#define BM   16       // query rows per block
#define NC   128      // n-chunk (K cols / V rows staged in smem)
#define SS   1024     // seq len
#define DD   64       // head dim
#define NBH  128      // B*H

static constexpr size_t O_ELEMS = (size_t)NBH * SS * DD;   // 8388608
static constexpr size_t W_ELEMS = (size_t)NBH * SS * SS;   // 134217728

// smem: Ss[BM][SS] (64KB) + Qdup[BM][DD] float2 (8KB) + KV[64*128] (32KB)
static constexpr int SMEM_BYTES = BM * SS * 4 + BM * DD * 8 + DD * NC * 4; // 106496

// ---- packed-f32x2 / shared-memory primitives ----
__device__ __forceinline__ unsigned long long lds_b64(unsigned a) {
    unsigned long long v;
    asm volatile("ld.shared.b64 %0, [%1];" : "=l"(v) : "r"(a));
    return v;
}
__device__ __forceinline__ float lds_f32(unsigned a) {
    float v;
    asm volatile("ld.shared.f32 %0, [%1];" : "=f"(v) : "r"(a));
    return v;
}
__device__ __forceinline__ void lds_v2u64(unsigned a, unsigned long long& x, unsigned long long& y) {
    asm volatile("ld.shared.v2.u64 {%0, %1}, [%2];" : "=l"(x), "=l"(y) : "r"(a));
}
// d.lo += a.lo*b.lo ; d.hi += a.hi*b.hi   (packed fp32x2 FMA, sm_100+)
__device__ __forceinline__ void ffma2(unsigned long long& d, unsigned long long a, unsigned long long b) {
    asm volatile("fma.rn.f32x2 %0, %1, %2, %0;" : "+l"(d) : "l"(a), "l"(b));
}
__device__ __forceinline__ unsigned long long pack2(float x) {
    unsigned long long v;
    asm volatile("mov.b64 %0, {%1, %1};" : "=l"(v) : "f"(x));
    return v;
}
__device__ __forceinline__ float2 unpk(unsigned long long v) {
    float2 r;
    asm volatile("mov.b64 {%0, %1}, %2;" : "=f"(r.x), "=f"(r.y) : "l"(v));
    return r;
}

__global__ __launch_bounds__(TB, 2)
void attn_fused_kernel(const float* __restrict__ q,      // [BH][S][D]
                       const float* __restrict__ kmat,   // [BH][D][S]  (already K^T-friendly)
                       const float* __restrict__ v,      // [BH][S][D]
                       const float* __restrict__ prev,   // [BH][S][S]
                       const float* __restrict__ mask,   // [S][S] broadcast
                       const float* __restrict__ scalep, // scalar
                       float* __restrict__ out_o,
                       float* __restrict__ out_w,
                       float* __restrict__ out_s)
{
    extern __shared__ float smem[];
    float*  Ss  = smem;                         // [BM][SS] scores -> weights
    float2* Qd  = (float2*)(smem + BM * SS);    // [BM][DD] Q duplicated (x,x) for f32x2
    float*  KV  = smem + BM * SS + BM * DD * 2; // [DD][NC] for K, reused as [NC][DD] for V

    const int tid   = threadIdx.x;
    const int bh    = blockIdx.y;
    const int qbase = blockIdx.x * BM;
    const float scale = scalep[0];

    const float* qg = q    + (size_t)bh * SS * DD;
    const float* kg = kmat + (size_t)bh * DD * SS;
    const float* vg = v    + (size_t)bh * SS * DD;
    const float* pg = prev + (size_t)bh * SS * SS;
    float* og = out_o + (size_t)bh * SS * DD;
    float* wg = out_w + (size_t)bh * SS * SS;
    float* sg = out_s + (size_t)bh * SS * SS;

    const unsigned ss_base = (unsigned)__cvta_generic_to_shared(Ss);
    const unsigned qd_base = (unsigned)__cvta_generic_to_shared(Qd);
    const unsigned kv_base = (unsigned)__cvta_generic_to_shared(KV);

    // ---- load Q tile, duplicated into both f32x2 lanes ----
    #pragma unroll
    for (int i = tid; i < BM * DD; i += TB) {
        int r = i >> 6, kk = i & 63;
        float val = qg[(size_t)(qbase + r) * DD + kk];
        Qd[r * DD + kk] = make_float2(val, val);
    }

    // ================= scores = (Q @ K) * mask * scale + prev =================
    // 256 threads: colg 0..31 -> 4 cols, rowg 0..7 -> 2 rows (warp == one row pair)
    const int colg = tid & 31;
    const int rowg = tid >> 5;
    const int r0   = rowg * 2;
    const unsigned qa0 = qd_base + (unsigned)(r0 * DD) * 8u;
    const unsigned qa1 = qa0 + DD * 8u;
    const unsigned bb0 = kv_base + (unsigned)(colg * 4) * 4u;

    for (int nb = 0; nb < SS; nb += NC) {
        __syncthreads();  // protects KV + (first iter) Qd
        // stage K chunk [DD][NC]
        #pragma unroll
        for (int i = tid; i < DD * (NC / 4); i += TB) {
            int row = i >> 5, c4 = i & 31;
            float4 t = *(const float4*)&kg[(size_t)row * SS + nb + c4 * 4];
            *(float4*)&KV[row * NC + c4 * 4] = t;
        }
        __syncthreads();

        unsigned long long acc00 = 0, acc01 = 0, acc10 = 0, acc11 = 0;
        #pragma unroll 16
        for (int kk = 0; kk < DD; kk++) {
            unsigned long long a0 = lds_b64(qa0 + kk * 8u);           // broadcast
            unsigned long long a1 = lds_b64(qa1 + kk * 8u);           // broadcast
            unsigned long long b01, b23;
            lds_v2u64(bb0 + (unsigned)kk * (NC * 4u), b01, b23);      // 16B vector
            ffma2(acc00, a0, b01); ffma2(acc01, a0, b23);
            ffma2(acc10, a1, b01); ffma2(acc11, a1, b23);
        }

        // epilogue: *mask*scale+prev, write scores to gmem + smem
        const int gc = nb + colg * 4;
        #pragma unroll
        for (int rr = 0; rr < 2; rr++) {
            float2 cA = unpk(rr ? acc10 : acc00);
            float2 cB = unpk(rr ? acc11 : acc01);
            const int gr = qbase + r0 + rr;
            float4 mk = *(const float4*)&mask[(size_t)gr * SS + gc];
            float4 pv = *(const float4*)&pg[(size_t)gr * SS + gc];
            float4 sc;
            sc.x = fmaf(cA.x * mk.x, scale, pv.x);
            sc.y = fmaf(cA.y * mk.y, scale, pv.y);
            sc.z = fmaf(cB.x * mk.z, scale, pv.z);
            sc.w = fmaf(cB.y * mk.w, scale, pv.w);
            *(float4*)&sg[(size_t)gr * SS + gc] = sc;
            *(float4*)&Ss[(r0 + rr) * SS + gc] = sc;
        }
    }
    __syncthreads();

    // ================= softmax per row (warp w handles rows w, w+8) =================
    const int warp = tid >> 5, lane = tid & 31;
    #pragma unroll
    for (int r = warp; r < BM; r += 8) {
        float* row = &Ss[r * SS];
        float m = -3.402823466e38f;
        for (int i = lane; i < SS; i += 32) m = fmaxf(m, row[i]);
        #pragma unroll
        for (int o = 16; o > 0; o >>= 1) m = fmaxf(m, __shfl_xor_sync(0xffffffffu, m, o));
        float sum = 0.f;
        for (int i = lane; i < SS; i += 32) {
            float e = exp2f((row[i] - m) * 1.4426950408889634f);
            row[i] = e; sum += e;
        }
        #pragma unroll
        for (int o = 16; o > 0; o >>= 1) sum += __shfl_xor_sync(0xffffffffu, sum, o);
        const float inv = 1.0f / sum;
        float* wrow = &wg[(size_t)(qbase + r) * SS];
        for (int i = lane; i < SS; i += 32) {
            float w = row[i] * inv;
            row[i] = w;          // keep normalized weights in smem for PV
            wrow[i] = w;         // write attn_weights
        }
    }

    // ================= out = W @ V =================
    // 256 threads: pcol 0..15 -> 4 cols, prow 0..15 -> 1 row. acc lives across chunks.
    const int pcol = tid & 15;
    const int prow = tid >> 4;
    unsigned long long o01 = 0, o23 = 0;
    const unsigned va0 = kv_base + (unsigned)(pcol * 4) * 4u;
    for (int sb = 0; sb < SS; sb += NC) {
        __syncthreads();  // orders softmax writes / prior-chunk V reads before restage
        #pragma unroll
        for (int i = tid; i < NC * (DD / 4); i += TB) {
            int row = i >> 4, c4 = i & 15;
            float4 t = *(const float4*)&vg[(size_t)(sb + row) * DD + c4 * 4];
            *(float4*)&KV[row * DD + c4 * 4] = t;
        }
        __syncthreads();
        const unsigned wa = ss_base + (unsigned)(prow * SS + sb) * 4u;
        #pragma unroll 16
        for (int s = 0; s < NC; s++) {
            float a = lds_f32(wa + s * 4u);                         // broadcast
            unsigned long long ap = pack2(a);
            unsigned long long b01, b23;
            lds_v2u64(va0 + (unsigned)s * (DD * 4u), b01, b23);
            ffma2(o01, ap, b01); ffma2(o23, ap, b23);
        }
    }
    float2 r01 = unpk(o01), r23 = unpk(o23);
    float4 ov = make_float4(r01.x, r01.y, r23.x, r23.y);
    *(float4*)&og[(size_t)(qbase + prow) * DD + pcol * 4] = ov;
}

extern "C" void kernel_launch(void* const* d_in, const int* in_sizes, int n_in,
                              void* d_out, int out_size) {
    (void)in_sizes; (void)n_in; (void)out_size;
    const float* q     = (const float*)d_in[0];
    const float* k     = (const float*)d_in[1];
    const float* v     = (const float*)d_in[2];
    const float* prev  = (const float*)d_in[3];
    const float* mask  = (const float*)d_in[4];
    const float* scale = (const float*)d_in[5];

    float* out   = (float*)d_out;
    float* out_o = out;                     // [B,H,S,D]
    float* out_w = out + O_ELEMS;           // [B,H,S,S]
    float* out_s = out_w + W_ELEMS;         // [B,H,S,S]

    cudaFuncSetAttribute(attn_fused_kernel,
                         cudaFuncAttributeMaxDynamicSharedMemorySize, SMEM_BYTES);

    dim3 grid(SS / BM, NBH);  // (64, 128) = 8192 blocks
    attn_fused_kernel<<<grid, TB, SMEM_BYTES>>>(q, k, v, prev, mask, scale,
                                                out_o, out_w, out_s);
}